// round 1
// baseline (speedup 1.0000x reference)
#include <cuda_runtime.h>

#define FULL 0xffffffffu

// KGCN fused kernel: one CTA per batch element, 256 threads = 4 groups x 64.
// Key trick: only NR=32 relations exist -> precompute urel[r] = dot(user, rel_emb[r])
// so all attention scores are lookups. W kept per-thread in 64 registers (one
// output column each) so each 64x64 matvec is 16 broadcast LDS.128 + 64 FFMA.
__global__ void __launch_bounds__(256, 2) kgcn_kernel(
    const int* __restrict__ U, const int* __restrict__ V,
    const int* __restrict__ adj_ent, const int* __restrict__ adj_rel,
    const float* __restrict__ usr_emb, const float* __restrict__ rel_emb,
    const float* __restrict__ ent_emb, const float* __restrict__ Wg,
    const float* __restrict__ bg, float* __restrict__ out, int NR)
{
    __shared__ float user_sh[64];
    __shared__ float urel_sh[64];
    __shared__ int   nbr_sh[272];   // [0..255]=hop2 ents, [256..271]=hop1 ents
    __shared__ int   rel_sh[272];   // [0..255]=hop1 rels, [256..271]=hop0 rels
    __shared__ float attn0_sh[16];
    __shared__ float h1_sh[16 * 64];
    __shared__ float h0_sh[64];
    __shared__ float xs_sh[4][64];
    __shared__ float Wsh[4096];
    __shared__ float red_sh[2];

    const int tid  = threadIdx.x;
    const int g    = tid >> 6;        // group 0..3
    const int col  = tid & 63;        // d / output column
    const int lane = tid & 31;
    const int wg   = (tid >> 5) & 1;  // warp within group
    const int b    = blockIdx.x;

    const int vidx = V[b];
    const int uidx = U[b];

    // ---- Phase A: user row, hop-1 adjacency, stage W ----
    if (tid < 64) user_sh[tid] = usr_emb[(long)uidx * 64 + tid];
    if (tid < 16) {
        nbr_sh[256 + tid] = adj_ent[(long)vidx * 16 + tid];
        rel_sh[256 + tid] = adj_rel[(long)vidx * 16 + tid];
    }
    {
        const float4* W4 = (const float4*)Wg;
        float4* Ws4 = (float4*)Wsh;
        #pragma unroll
        for (int i = 0; i < 4; i++) Ws4[tid + 256 * i] = W4[tid + 256 * i];
    }
    const float breg = bg[col];
    __syncthreads();

    // ---- Phase B: hop-2 adjacency, urel table, W -> registers ----
    {
        int e = nbr_sh[256 + (tid >> 4)];
        nbr_sh[tid] = adj_ent[(long)e * 16 + (tid & 15)];
        rel_sh[tid] = adj_rel[(long)e * 16 + (tid & 15)];
    }
    {
        // urel[r] = dot(user, rel_emb[r]); 8 threads per relation, coalesced float4
        int r = tid >> 3;
        int c = (tid & 7) * 8;
        float part = 0.f;
        if (r < NR) {
            const float4* rp = (const float4*)(rel_emb + (long)r * 64 + c);
            float4 aa = rp[0], bb = rp[1];
            part = aa.x * user_sh[c + 0] + aa.y * user_sh[c + 1]
                 + aa.z * user_sh[c + 2] + aa.w * user_sh[c + 3]
                 + bb.x * user_sh[c + 4] + bb.y * user_sh[c + 5]
                 + bb.z * user_sh[c + 6] + bb.w * user_sh[c + 7];
        }
        part += __shfl_down_sync(FULL, part, 4);
        part += __shfl_down_sync(FULL, part, 2);
        part += __shfl_down_sync(FULL, part, 1);
        if ((tid & 7) == 0 && r < NR) urel_sh[r] = part;
    }
    float Wreg[64];
    #pragma unroll
    for (int d = 0; d < 64; d++) Wreg[d] = Wsh[d * 64 + col];
    __syncthreads();

    // ---- Phase C: iter-0 — 17 rows (16 hop-1 rows + 1 hop-0 row) ----
    for (int row = g; row < 17; row += 4) {
        const bool hop1 = (row < 16);
        const int base = hop1 ? (row << 4) : 256;
        const int selfIdx = hop1 ? nbr_sh[256 + row] : vidx;

        // gather neighbor embedding values for my dim (col)
        float nv[16];
        {
            const int4* p4 = (const int4*)&nbr_sh[base];
            #pragma unroll
            for (int q = 0; q < 4; q++) {
                int4 t = p4[q];
                nv[4 * q + 0] = ent_emb[(long)t.x * 64 + col];
                nv[4 * q + 1] = ent_emb[(long)t.y * 64 + col];
                nv[4 * q + 2] = ent_emb[(long)t.z * 64 + col];
                nv[4 * q + 3] = ent_emb[(long)t.w * 64 + col];
            }
        }
        float selfv = ent_emb[(long)selfIdx * 64 + col];

        // softmax over 16 neighbors (both warps compute identically)
        float s = -1e30f;
        if (lane < 16) s = urel_sh[rel_sh[base + lane]];
        float mx = s;
        #pragma unroll
        for (int o = 16; o > 0; o >>= 1) mx = fmaxf(mx, __shfl_xor_sync(FULL, mx, o));
        float ev = (lane < 16) ? __expf(s - mx) : 0.f;
        float sum = ev;
        #pragma unroll
        for (int o = 16; o > 0; o >>= 1) sum += __shfl_xor_sync(FULL, sum, o);
        float p = __fdividef(ev, sum);
        if (!hop1 && wg == 0 && lane < 16) attn0_sh[lane] = p;  // reused in iter-1

        float agg = 0.f;
        #pragma unroll
        for (int k = 0; k < 16; k++)
            agg = fmaf(__shfl_sync(FULL, p, k), nv[k], agg);
        float x = selfv + agg;

        // matvec: y = (self+agg) @ W + b, W column in registers
        xs_sh[g][col] = x;
        asm volatile("bar.sync %0, %1;" :: "r"(g + 1), "r"(64) : "memory");
        float y = breg;
        {
            const float4* x4 = (const float4*)xs_sh[g];
            #pragma unroll
            for (int q = 0; q < 16; q++) {
                float4 xv = x4[q];
                y = fmaf(xv.x, Wreg[4 * q + 0], y);
                y = fmaf(xv.y, Wreg[4 * q + 1], y);
                y = fmaf(xv.z, Wreg[4 * q + 2], y);
                y = fmaf(xv.w, Wreg[4 * q + 3], y);
            }
        }
        asm volatile("bar.sync %0, %1;" :: "r"(g + 1), "r"(64) : "memory");
        float h = __fdividef(1.f, 1.f + __expf(-y));  // sigmoid (iter 0)
        if (hop1) h1_sh[(row << 6) + col] = h;
        else      h0_sh[col] = h;
    }
    __syncthreads();

    // ---- Phase D: iter-1 hop-0 (group 0 only) + final score ----
    if (g == 0) {
        float agg = 0.f;
        #pragma unroll
        for (int k = 0; k < 16; k++)
            agg = fmaf(attn0_sh[k], h1_sh[(k << 6) + col], agg);
        float x = h0_sh[col] + agg;
        xs_sh[0][col] = x;
        asm volatile("bar.sync 1, 64;" ::: "memory");
        float y = breg;
        const float4* x4 = (const float4*)xs_sh[0];
        #pragma unroll
        for (int q = 0; q < 16; q++) {
            float4 xv = x4[q];
            y = fmaf(xv.x, Wreg[4 * q + 0], y);
            y = fmaf(xv.y, Wreg[4 * q + 1], y);
            y = fmaf(xv.z, Wreg[4 * q + 2], y);
            y = fmaf(xv.w, Wreg[4 * q + 3], y);
        }
        float item = tanhf(y);
        float t = user_sh[col] * item;
        #pragma unroll
        for (int o = 16; o > 0; o >>= 1) t += __shfl_xor_sync(FULL, t, o);
        if (lane == 0) red_sh[wg] = t;
        asm volatile("bar.sync 1, 64;" ::: "memory");
        if (tid == 0)
            out[b] = __fdividef(1.f, 1.f + __expf(-(red_sh[0] + red_sh[1])));
    }
}

extern "C" void kernel_launch(void* const* d_in, const int* in_sizes, int n_in,
                              void* d_out, int out_size) {
    const int*   U       = (const int*)d_in[0];
    const int*   V       = (const int*)d_in[1];
    const int*   adj_ent = (const int*)d_in[2];
    const int*   adj_rel = (const int*)d_in[3];
    const float* usr_emb = (const float*)d_in[4];
    const float* rel_emb = (const float*)d_in[5];
    const float* ent_emb = (const float*)d_in[6];
    const float* W       = (const float*)d_in[7];
    const float* bvec    = (const float*)d_in[8];
    float* out = (float*)d_out;

    const int B  = in_sizes[0];
    const int NR = in_sizes[5] / 64;

    kgcn_kernel<<<B, 256>>>(U, V, adj_ent, adj_rel, usr_emb, rel_emb,
                            ent_emb, W, bvec, out, NR);
}

// round 2
// speedup vs baseline: 1.2935x; 1.2935x over previous
#include <cuda_runtime.h>

#define FULL 0xffffffffu

__device__ __forceinline__ float sigmoidf_(float y) {
    return __fdividef(1.f, 1.f + __expf(-y));
}

// KGCN fused: one CTA per batch element, 256 threads.
// Phase C: warp w independently computes softmax + aggregation for rows 2w,2w+1
//          (each lane covers cols lane, lane+32). Warp 0 also does hop-0 (row 16).
// Matvec:  thread owns output column (W column in 64 regs), 4 rows interleaved.
__global__ void __launch_bounds__(256, 2) kgcn_kernel(
    const int* __restrict__ U, const int* __restrict__ V,
    const int* __restrict__ adj_ent, const int* __restrict__ adj_rel,
    const float* __restrict__ usr_emb, const float* __restrict__ rel_emb,
    const float* __restrict__ ent_emb, const float* __restrict__ Wg,
    const float* __restrict__ bg, float* __restrict__ out, int NR)
{
    __shared__ float user_sh[64];
    __shared__ float urel_sh[32];
    __shared__ int   nbr_sh[272];    // [0..255] hop2 ents, [256..271] hop1 ents
    __shared__ int   rel_sh[272];    // [0..255] hop1 rels, [256..271] hop0 rels
    __shared__ float attn16_sh[16];  // hop-0 attention (reused in iter-1)
    __shared__ float x_sh[17][64];   // pre-matvec activations
    __shared__ float h1_sh[16 * 64]; // iter-0 hop-1 outputs
    __shared__ float red_sh[2];

    const int tid  = threadIdx.x;
    const int g    = tid >> 6;
    const int col  = tid & 63;
    const int lane = tid & 31;
    const int w    = tid >> 5;       // warp 0..7
    const int b    = blockIdx.x;

    const int vidx = V[b];
    const int uidx = U[b];

    // ---- Phase A: user row, hop-1 adjacency; W column -> registers ----
    if (tid < 64) user_sh[tid] = usr_emb[uidx * 64 + tid];
    if (tid >= 64 && tid < 80) {
        int j = tid - 64;
        nbr_sh[256 + j] = adj_ent[vidx * 16 + j];
        rel_sh[256 + j] = adj_rel[vidx * 16 + j];
    }
    float Wreg[64];
    #pragma unroll
    for (int d = 0; d < 64; d++) Wreg[d] = Wg[d * 64 + col];
    const float breg = bg[col];
    __syncthreads();

    // ---- Phase B: hop-2 adjacency + urel table ----
    {
        int e = nbr_sh[256 + (tid >> 4)];
        nbr_sh[tid] = adj_ent[e * 16 + (tid & 15)];
        rel_sh[tid] = adj_rel[e * 16 + (tid & 15)];
    }
    {
        int r = tid >> 3;
        int c = (tid & 7) * 8;
        float part = 0.f;
        if (r < NR) {
            const float4* rp = (const float4*)(rel_emb + r * 64 + c);
            float4 aa = rp[0], bb = rp[1];
            part = aa.x * user_sh[c + 0] + aa.y * user_sh[c + 1]
                 + aa.z * user_sh[c + 2] + aa.w * user_sh[c + 3]
                 + bb.x * user_sh[c + 4] + bb.y * user_sh[c + 5]
                 + bb.z * user_sh[c + 6] + bb.w * user_sh[c + 7];
        }
        part += __shfl_down_sync(FULL, part, 4);
        part += __shfl_down_sync(FULL, part, 2);
        part += __shfl_down_sync(FULL, part, 1);
        if ((tid & 7) == 0 && r < NR) urel_sh[r] = part;
    }
    __syncthreads();

    // ---- Phase C: fused softmax + aggregation, per-warp independent ----
    {
        const int r0 = 2 * w, r1 = 2 * w + 1;
        const int half = lane >> 4, k15 = lane & 15;
        const int myrow = 2 * w + half;

        // softmax for rows r0 (lanes 0-15) and r1 (lanes 16-31), width-16 shuffles
        float s = urel_sh[rel_sh[(myrow << 4) + k15]];
        float mx = s;
        mx = fmaxf(mx, __shfl_xor_sync(FULL, mx, 8));
        mx = fmaxf(mx, __shfl_xor_sync(FULL, mx, 4));
        mx = fmaxf(mx, __shfl_xor_sync(FULL, mx, 2));
        mx = fmaxf(mx, __shfl_xor_sync(FULL, mx, 1));
        float ev = __expf(s - mx);
        float sm = ev;
        sm += __shfl_xor_sync(FULL, sm, 8);
        sm += __shfl_xor_sync(FULL, sm, 4);
        sm += __shfl_xor_sync(FULL, sm, 2);
        sm += __shfl_xor_sync(FULL, sm, 1);
        float p = __fdividef(ev, sm);

        // aggregation: lane covers cols (lane, lane+32) for rows r0 and r1
        const int si0 = nbr_sh[256 + r0] << 6;
        const int si1 = nbr_sh[256 + r1] << 6;
        float s0a = ent_emb[si0 + lane], s0b = ent_emb[si0 + lane + 32];
        float s1a = ent_emb[si1 + lane], s1b = ent_emb[si1 + lane + 32];
        float A0a = 0.f, A0b = 0.f, A1a = 0.f, A1b = 0.f;
        #pragma unroll
        for (int k = 0; k < 16; k++) {
            float p0 = __shfl_sync(FULL, p, k);
            float p1 = __shfl_sync(FULL, p, 16 + k);
            const float* e0 = ent_emb + (nbr_sh[(r0 << 4) + k] << 6);
            const float* e1 = ent_emb + (nbr_sh[(r1 << 4) + k] << 6);
            A0a = fmaf(p0, e0[lane],      A0a);
            A0b = fmaf(p0, e0[lane + 32], A0b);
            A1a = fmaf(p1, e1[lane],      A1a);
            A1b = fmaf(p1, e1[lane + 32], A1b);
        }
        x_sh[r0][lane]      = s0a + A0a;
        x_sh[r0][lane + 32] = s0b + A0b;
        x_sh[r1][lane]      = s1a + A1a;
        x_sh[r1][lane + 32] = s1b + A1b;

        if (w == 0) {
            // hop-0 (row 16): both halves compute identical softmax (uniform)
            float s2 = urel_sh[rel_sh[256 + k15]];
            float mx2 = s2;
            mx2 = fmaxf(mx2, __shfl_xor_sync(FULL, mx2, 8));
            mx2 = fmaxf(mx2, __shfl_xor_sync(FULL, mx2, 4));
            mx2 = fmaxf(mx2, __shfl_xor_sync(FULL, mx2, 2));
            mx2 = fmaxf(mx2, __shfl_xor_sync(FULL, mx2, 1));
            float ev2 = __expf(s2 - mx2);
            float sm2 = ev2;
            sm2 += __shfl_xor_sync(FULL, sm2, 8);
            sm2 += __shfl_xor_sync(FULL, sm2, 4);
            sm2 += __shfl_xor_sync(FULL, sm2, 2);
            sm2 += __shfl_xor_sync(FULL, sm2, 1);
            float p2 = __fdividef(ev2, sm2);
            if (lane < 16) attn16_sh[lane] = p2;   // reused in iter-1

            const int siv = vidx << 6;
            float sva = ent_emb[siv + lane], svb = ent_emb[siv + lane + 32];
            float Ba = 0.f, Bb = 0.f;
            #pragma unroll
            for (int k = 0; k < 16; k++) {
                float pk = __shfl_sync(FULL, p2, k);
                const float* ek = ent_emb + (nbr_sh[256 + k] << 6);
                Ba = fmaf(pk, ek[lane],      Ba);
                Bb = fmaf(pk, ek[lane + 32], Bb);
            }
            x_sh[16][lane]      = sva + Ba;
            x_sh[16][lane + 32] = svb + Bb;
        }
    }
    __syncthreads();

    // ---- Matvec: thread owns column `col`, 4 rows interleaved ----
    {
        const int r = 4 * g;
        float y0 = breg, y1 = breg, y2 = breg, y3 = breg;
        const float4* xa = (const float4*)x_sh[r + 0];
        const float4* xb = (const float4*)x_sh[r + 1];
        const float4* xc = (const float4*)x_sh[r + 2];
        const float4* xd = (const float4*)x_sh[r + 3];
        #pragma unroll
        for (int q = 0; q < 16; q++) {
            float4 va = xa[q], vb = xb[q], vc = xc[q], vd = xd[q];
            float w0 = Wreg[4*q+0], w1 = Wreg[4*q+1], w2 = Wreg[4*q+2], w3 = Wreg[4*q+3];
            y0 = fmaf(va.x, w0, y0); y0 = fmaf(va.y, w1, y0);
            y0 = fmaf(va.z, w2, y0); y0 = fmaf(va.w, w3, y0);
            y1 = fmaf(vb.x, w0, y1); y1 = fmaf(vb.y, w1, y1);
            y1 = fmaf(vb.z, w2, y1); y1 = fmaf(vb.w, w3, y1);
            y2 = fmaf(vc.x, w0, y2); y2 = fmaf(vc.y, w1, y2);
            y2 = fmaf(vc.z, w2, y2); y2 = fmaf(vc.w, w3, y2);
            y3 = fmaf(vd.x, w0, y3); y3 = fmaf(vd.y, w1, y3);
            y3 = fmaf(vd.z, w2, y3); y3 = fmaf(vd.w, w3, y3);
        }
        h1_sh[(r + 0) * 64 + col] = sigmoidf_(y0);
        h1_sh[(r + 1) * 64 + col] = sigmoidf_(y1);
        h1_sh[(r + 2) * 64 + col] = sigmoidf_(y2);
        h1_sh[(r + 3) * 64 + col] = sigmoidf_(y3);
    }
    __syncthreads();

    // ---- Phase D: hop-0 matvec, iter-1, final score (group 0 only) ----
    if (g == 0) {
        float y = breg;
        {
            const float4* xe = (const float4*)x_sh[16];
            #pragma unroll
            for (int q = 0; q < 16; q++) {
                float4 v = xe[q];
                y = fmaf(v.x, Wreg[4*q+0], y);
                y = fmaf(v.y, Wreg[4*q+1], y);
                y = fmaf(v.z, Wreg[4*q+2], y);
                y = fmaf(v.w, Wreg[4*q+3], y);
            }
        }
        float h0 = sigmoidf_(y);

        float a0 = 0.f, a1 = 0.f, a2 = 0.f, a3 = 0.f;
        #pragma unroll
        for (int k = 0; k < 16; k += 4) {
            a0 = fmaf(attn16_sh[k + 0], h1_sh[(k + 0) * 64 + col], a0);
            a1 = fmaf(attn16_sh[k + 1], h1_sh[(k + 1) * 64 + col], a1);
            a2 = fmaf(attn16_sh[k + 2], h1_sh[(k + 2) * 64 + col], a2);
            a3 = fmaf(attn16_sh[k + 3], h1_sh[(k + 3) * 64 + col], a3);
        }
        x_sh[0][col] = h0 + ((a0 + a1) + (a2 + a3));
        asm volatile("bar.sync 1, 64;" ::: "memory");

        float y2 = breg;
        {
            const float4* xf = (const float4*)x_sh[0];
            #pragma unroll
            for (int q = 0; q < 16; q++) {
                float4 v = xf[q];
                y2 = fmaf(v.x, Wreg[4*q+0], y2);
                y2 = fmaf(v.y, Wreg[4*q+1], y2);
                y2 = fmaf(v.z, Wreg[4*q+2], y2);
                y2 = fmaf(v.w, Wreg[4*q+3], y2);
            }
        }
        float item = tanhf(y2);
        float t = user_sh[col] * item;
        t += __shfl_xor_sync(FULL, t, 16);
        t += __shfl_xor_sync(FULL, t, 8);
        t += __shfl_xor_sync(FULL, t, 4);
        t += __shfl_xor_sync(FULL, t, 2);
        t += __shfl_xor_sync(FULL, t, 1);
        if (lane == 0) red_sh[w] = t;
        asm volatile("bar.sync 1, 64;" ::: "memory");
        if (tid == 0)
            out[b] = sigmoidf_(red_sh[0] + red_sh[1]);
    }
}

extern "C" void kernel_launch(void* const* d_in, const int* in_sizes, int n_in,
                              void* d_out, int out_size) {
    const int*   U       = (const int*)d_in[0];
    const int*   V       = (const int*)d_in[1];
    const int*   adj_ent = (const int*)d_in[2];
    const int*   adj_rel = (const int*)d_in[3];
    const float* usr_emb = (const float*)d_in[4];
    const float* rel_emb = (const float*)d_in[5];
    const float* ent_emb = (const float*)d_in[6];
    const float* W       = (const float*)d_in[7];
    const float* bvec    = (const float*)d_in[8];
    float* out = (float*)d_out;

    const int B  = in_sizes[0];
    const int NR = in_sizes[5] / 64;

    kgcn_kernel<<<B, 256>>>(U, V, adj_ent, adj_rel, usr_emb, rel_emb,
                            ent_emb, W, bvec, out, NR);
}

// round 3
// speedup vs baseline: 1.5549x; 1.2021x over previous
#include <cuda_runtime.h>

#define FULL 0xffffffffu

__device__ __forceinline__ float sigmoidf_(float y) {
    return __fdividef(1.f, 1.f + __expf(-y));
}

// KGCN fused: one CTA per batch element, 256 threads = 4 groups of 64.
// W split across group pairs: each thread holds a HALF-column of W (32 regs)
// -> ~80 regs/thread -> 3 CTAs/SM (24 warps) for latency hiding.
// Matvec = two partial dots (d 0-31 / d 32-63) combined via one smem add.
__global__ void __launch_bounds__(256, 3) kgcn_kernel(
    const int* __restrict__ U, const int* __restrict__ V,
    const int* __restrict__ adj_ent, const int* __restrict__ adj_rel,
    const float* __restrict__ usr_emb, const float* __restrict__ rel_emb,
    const float* __restrict__ ent_emb, const float* __restrict__ Wg,
    const float* __restrict__ bg, float* __restrict__ out, int NR)
{
    __shared__ float user_sh[64];
    __shared__ float urel_sh[32];
    __shared__ int   nbr_sh[272];    // [0..255] hop2 ents, [256..271] hop1 ents
    __shared__ int   rel_sh[272];    // [0..255] hop1 rels, [256..271] hop0 rels
    __shared__ float attn16_sh[16];  // hop-0 attention (reused in iter-1)
    __shared__ float x_sh[17][64];   // pre-matvec activations
    __shared__ float part_sh[17][64];// half-1 partial matvec sums
    __shared__ float h1_sh[16 * 64]; // iter-0 hop-1 outputs
    __shared__ float h0_sh[64];
    __shared__ float x2_sh[64];
    __shared__ float red_sh[2];

    const int tid  = threadIdx.x;
    const int g    = tid >> 6;       // group 0..3
    const int col  = tid & 63;
    const int lane = tid & 31;
    const int w    = tid >> 5;       // warp 0..7
    const int pair = g >> 1;         // 0 or 1
    const int half = g & 1;          // 0: d in [0,32), 1: d in [32,64)
    const int b    = blockIdx.x;

    const int vidx = V[b];
    const int uidx = U[b];

    // ---- Phase A: user row + hop-1 adjacency ----
    if (tid < 64) user_sh[tid] = usr_emb[uidx * 64 + tid];
    if (tid >= 64 && tid < 80) {
        int j = tid - 64;
        nbr_sh[256 + j] = adj_ent[vidx * 16 + j];
        rel_sh[256 + j] = adj_rel[vidx * 16 + j];
    }
    const float breg = bg[col];
    __syncthreads();

    // ---- Phase B: hop-2 adjacency + urel table ----
    {
        int e = nbr_sh[256 + (tid >> 4)];
        nbr_sh[tid] = adj_ent[e * 16 + (tid & 15)];
        rel_sh[tid] = adj_rel[e * 16 + (tid & 15)];
    }
    {
        int r = tid >> 3;
        int c = (tid & 7) * 8;
        float part = 0.f;
        if (r < NR) {
            const float4* rp = (const float4*)(rel_emb + r * 64 + c);
            float4 aa = rp[0], bb = rp[1];
            part = aa.x * user_sh[c + 0] + aa.y * user_sh[c + 1]
                 + aa.z * user_sh[c + 2] + aa.w * user_sh[c + 3]
                 + bb.x * user_sh[c + 4] + bb.y * user_sh[c + 5]
                 + bb.z * user_sh[c + 6] + bb.w * user_sh[c + 7];
        }
        part += __shfl_down_sync(FULL, part, 4);
        part += __shfl_down_sync(FULL, part, 2);
        part += __shfl_down_sync(FULL, part, 1);
        if ((tid & 7) == 0 && r < NR) urel_sh[r] = part;
    }
    __syncthreads();

    // ---- Phase C: fused softmax + aggregation, per-warp independent ----
    {
        const int r0 = 2 * w, r1 = 2 * w + 1;
        const int hlf = lane >> 4, k15 = lane & 15;
        const int myrow = 2 * w + hlf;

        float s = urel_sh[rel_sh[(myrow << 4) + k15]];
        float mx = s;
        mx = fmaxf(mx, __shfl_xor_sync(FULL, mx, 8));
        mx = fmaxf(mx, __shfl_xor_sync(FULL, mx, 4));
        mx = fmaxf(mx, __shfl_xor_sync(FULL, mx, 2));
        mx = fmaxf(mx, __shfl_xor_sync(FULL, mx, 1));
        float ev = __expf(s - mx);
        float sm = ev;
        sm += __shfl_xor_sync(FULL, sm, 8);
        sm += __shfl_xor_sync(FULL, sm, 4);
        sm += __shfl_xor_sync(FULL, sm, 2);
        sm += __shfl_xor_sync(FULL, sm, 1);
        float p = __fdividef(ev, sm);

        const int si0 = nbr_sh[256 + r0] << 6;
        const int si1 = nbr_sh[256 + r1] << 6;
        float s0a = ent_emb[si0 + lane], s0b = ent_emb[si0 + lane + 32];
        float s1a = ent_emb[si1 + lane], s1b = ent_emb[si1 + lane + 32];
        float A0a = 0.f, A0b = 0.f, A1a = 0.f, A1b = 0.f;
        #pragma unroll
        for (int k = 0; k < 16; k++) {
            float p0 = __shfl_sync(FULL, p, k);
            float p1 = __shfl_sync(FULL, p, 16 + k);
            const float* e0 = ent_emb + (nbr_sh[(r0 << 4) + k] << 6);
            const float* e1 = ent_emb + (nbr_sh[(r1 << 4) + k] << 6);
            A0a = fmaf(p0, e0[lane],      A0a);
            A0b = fmaf(p0, e0[lane + 32], A0b);
            A1a = fmaf(p1, e1[lane],      A1a);
            A1b = fmaf(p1, e1[lane + 32], A1b);
        }
        x_sh[r0][lane]      = s0a + A0a;
        x_sh[r0][lane + 32] = s0b + A0b;
        x_sh[r1][lane]      = s1a + A1a;
        x_sh[r1][lane + 32] = s1b + A1b;

        if (w == 0) {
            float s2 = urel_sh[rel_sh[256 + k15]];
            float mx2 = s2;
            mx2 = fmaxf(mx2, __shfl_xor_sync(FULL, mx2, 8));
            mx2 = fmaxf(mx2, __shfl_xor_sync(FULL, mx2, 4));
            mx2 = fmaxf(mx2, __shfl_xor_sync(FULL, mx2, 2));
            mx2 = fmaxf(mx2, __shfl_xor_sync(FULL, mx2, 1));
            float ev2 = __expf(s2 - mx2);
            float sm2 = ev2;
            sm2 += __shfl_xor_sync(FULL, sm2, 8);
            sm2 += __shfl_xor_sync(FULL, sm2, 4);
            sm2 += __shfl_xor_sync(FULL, sm2, 2);
            sm2 += __shfl_xor_sync(FULL, sm2, 1);
            float p2 = __fdividef(ev2, sm2);
            if (lane < 16) attn16_sh[lane] = p2;

            const int siv = vidx << 6;
            float sva = ent_emb[siv + lane], svb = ent_emb[siv + lane + 32];
            float Ba = 0.f, Bb = 0.f;
            #pragma unroll
            for (int k = 0; k < 16; k++) {
                float pk = __shfl_sync(FULL, p2, k);
                const float* ek = ent_emb + (nbr_sh[256 + k] << 6);
                Ba = fmaf(pk, ek[lane],      Ba);
                Bb = fmaf(pk, ek[lane + 32], Bb);
            }
            x_sh[16][lane]      = sva + Ba;
            x_sh[16][lane + 32] = svb + Bb;
        }
    }
    __syncthreads();

    // ---- W half-column -> 32 registers (loaded late to ease Phase C pressure) ----
    float Wreg[32];
    #pragma unroll
    for (int d = 0; d < 32; d++) Wreg[d] = Wg[(half * 32 + d) * 64 + col];

    // ---- Matvec: pair p handles rows 8p..8p+7 (+row 16 for pair 0), 8-9 accs ----
    {
        float acc[9];
        #pragma unroll
        for (int r = 0; r < 9; r++) acc[r] = 0.f;
        const int rbase = pair << 3;
        #pragma unroll
        for (int q = 0; q < 8; q++) {
            float w0 = Wreg[4*q+0], w1 = Wreg[4*q+1];
            float w2 = Wreg[4*q+2], w3 = Wreg[4*q+3];
            #pragma unroll
            for (int r = 0; r < 8; r++) {
                float4 v = *(const float4*)&x_sh[rbase + r][half * 32 + 4*q];
                acc[r] = fmaf(v.x, w0, acc[r]);
                acc[r] = fmaf(v.y, w1, acc[r]);
                acc[r] = fmaf(v.z, w2, acc[r]);
                acc[r] = fmaf(v.w, w3, acc[r]);
            }
            if (pair == 0) {
                float4 v = *(const float4*)&x_sh[16][half * 32 + 4*q];
                acc[8] = fmaf(v.x, w0, acc[8]);
                acc[8] = fmaf(v.y, w1, acc[8]);
                acc[8] = fmaf(v.z, w2, acc[8]);
                acc[8] = fmaf(v.w, w3, acc[8]);
            }
        }
        if (half == 1) {
            #pragma unroll
            for (int r = 0; r < 8; r++) part_sh[rbase + r][col] = acc[r];
            if (pair == 0) part_sh[16][col] = acc[8];
        }
        __syncthreads();
        if (half == 0) {
            #pragma unroll
            for (int r = 0; r < 8; r++)
                h1_sh[(rbase + r) * 64 + col] =
                    sigmoidf_(acc[r] + part_sh[rbase + r][col] + breg);
            if (pair == 0)
                h0_sh[col] = sigmoidf_(acc[8] + part_sh[16][col] + breg);
        }
    }
    __syncthreads();

    // ---- Phase D: iter-1 (threads 0..127 only) ----
    if (tid < 128) {
        if (tid < 64) {
            float a0 = 0.f, a1 = 0.f, a2 = 0.f, a3 = 0.f;
            #pragma unroll
            for (int k = 0; k < 16; k += 4) {
                a0 = fmaf(attn16_sh[k + 0], h1_sh[(k + 0) * 64 + col], a0);
                a1 = fmaf(attn16_sh[k + 1], h1_sh[(k + 1) * 64 + col], a1);
                a2 = fmaf(attn16_sh[k + 2], h1_sh[(k + 2) * 64 + col], a2);
                a3 = fmaf(attn16_sh[k + 3], h1_sh[(k + 3) * 64 + col], a3);
            }
            x2_sh[col] = h0_sh[col] + ((a0 + a1) + (a2 + a3));
        }
        asm volatile("bar.sync 1, 128;" ::: "memory");

        // pair matvec on x2: half h covers d in [32h, 32h+32)
        float y0 = 0.f, y1 = 0.f, y2a = 0.f, y3 = 0.f;
        {
            const float4* xv = (const float4*)&x2_sh[half * 32];
            #pragma unroll
            for (int q = 0; q < 8; q += 4) {
                float4 v0 = xv[q + 0], v1 = xv[q + 1], v2 = xv[q + 2], v3 = xv[q + 3];
                y0 = fmaf(v0.x, Wreg[4*q+0],  y0); y0 = fmaf(v0.y, Wreg[4*q+1],  y0);
                y0 = fmaf(v0.z, Wreg[4*q+2],  y0); y0 = fmaf(v0.w, Wreg[4*q+3],  y0);
                y1 = fmaf(v1.x, Wreg[4*q+4],  y1); y1 = fmaf(v1.y, Wreg[4*q+5],  y1);
                y1 = fmaf(v1.z, Wreg[4*q+6],  y1); y1 = fmaf(v1.w, Wreg[4*q+7],  y1);
                y2a = fmaf(v2.x, Wreg[4*q+8],  y2a); y2a = fmaf(v2.y, Wreg[4*q+9],  y2a);
                y2a = fmaf(v2.z, Wreg[4*q+10], y2a); y2a = fmaf(v2.w, Wreg[4*q+11], y2a);
                y3 = fmaf(v3.x, Wreg[4*q+12], y3); y3 = fmaf(v3.y, Wreg[4*q+13], y3);
                y3 = fmaf(v3.z, Wreg[4*q+14], y3); y3 = fmaf(v3.w, Wreg[4*q+15], y3);
            }
        }
        float yp = (y0 + y1) + (y2a + y3);
        if (half == 1) part_sh[0][col] = yp;
        asm volatile("bar.sync 1, 128;" ::: "memory");

        if (tid < 64) {
            float item = tanhf(yp + part_sh[0][col] + breg);
            float t = user_sh[col] * item;
            t += __shfl_xor_sync(FULL, t, 16);
            t += __shfl_xor_sync(FULL, t, 8);
            t += __shfl_xor_sync(FULL, t, 4);
            t += __shfl_xor_sync(FULL, t, 2);
            t += __shfl_xor_sync(FULL, t, 1);
            if (lane == 0) red_sh[w] = t;
            asm volatile("bar.sync 2, 64;" ::: "memory");
            if (tid == 0)
                out[b] = sigmoidf_(red_sh[0] + red_sh[1]);
        }
    }
}

extern "C" void kernel_launch(void* const* d_in, const int* in_sizes, int n_in,
                              void* d_out, int out_size) {
    const int*   U       = (const int*)d_in[0];
    const int*   V       = (const int*)d_in[1];
    const int*   adj_ent = (const int*)d_in[2];
    const int*   adj_rel = (const int*)d_in[3];
    const float* usr_emb = (const float*)d_in[4];
    const float* rel_emb = (const float*)d_in[5];
    const float* ent_emb = (const float*)d_in[6];
    const float* W       = (const float*)d_in[7];
    const float* bvec    = (const float*)d_in[8];
    float* out = (float*)d_out;

    const int B  = in_sizes[0];
    const int NR = in_sizes[5] / 64;

    kgcn_kernel<<<B, 256>>>(U, V, adj_ent, adj_rel, usr_emb, rel_emb,
                            ent_emb, W, bvec, out, NR);
}

// round 4
// speedup vs baseline: 1.5581x; 1.0021x over previous
#include <cuda_runtime.h>

#define FULL 0xffffffffu

__device__ __forceinline__ float sigmoidf_(float y) {
    return __fdividef(1.f, 1.f + __expf(-y));
}

// KGCN fused: one CTA per batch element, 256 threads = 4 groups of 64.
// Phase C gathers use LDG.128: each 16-lane half owns a row, lane owns a
// float4 chunk -> 17 wide loads per warp instead of 68 scalar loads.
// W split across group pairs (half-column in 32 regs) -> 3 CTAs/SM.
__global__ void __launch_bounds__(256, 3) kgcn_kernel(
    const int* __restrict__ U, const int* __restrict__ V,
    const int* __restrict__ adj_ent, const int* __restrict__ adj_rel,
    const float* __restrict__ usr_emb, const float* __restrict__ rel_emb,
    const float* __restrict__ ent_emb, const float* __restrict__ Wg,
    const float* __restrict__ bg, float* __restrict__ out, int NR)
{
    __shared__ float user_sh[64];
    __shared__ float urel_sh[32];
    __shared__ int   nbr_sh[272];    // [0..255] hop2 ents, [256..271] hop1 ents
    __shared__ int   rel_sh[272];    // [0..255] hop1 rels, [256..271] hop0 rels
    __shared__ float attn16_sh[16];  // hop-0 attention (reused in iter-1)
    __shared__ __align__(16) float x_sh[17][64];    // pre-matvec activations
    __shared__ __align__(16) float part_sh[17][64]; // half-1 partial matvec sums
    __shared__ __align__(16) float h1_sh[16 * 64];  // iter-0 hop-1 outputs
    __shared__ float h0_sh[64];
    __shared__ __align__(16) float x2_sh[64];
    __shared__ float red_sh[2];

    const int tid  = threadIdx.x;
    const int g    = tid >> 6;       // group 0..3
    const int col  = tid & 63;
    const int lane = tid & 31;
    const int w    = tid >> 5;       // warp 0..7
    const int pair = g >> 1;         // 0 or 1
    const int half = g & 1;          // 0: d in [0,32), 1: d in [32,64)
    const int b    = blockIdx.x;

    const int vidx = V[b];
    const int uidx = U[b];

    // ---- Phase A: user row + hop-1 adjacency ----
    if (tid < 64) user_sh[tid] = usr_emb[uidx * 64 + tid];
    if (tid >= 64 && tid < 80) {
        int j = tid - 64;
        nbr_sh[256 + j] = adj_ent[vidx * 16 + j];
        rel_sh[256 + j] = adj_rel[vidx * 16 + j];
    }
    const float breg = bg[col];
    __syncthreads();

    // ---- Phase B: hop-2 adjacency + urel table ----
    {
        int e = nbr_sh[256 + (tid >> 4)];
        nbr_sh[tid] = adj_ent[e * 16 + (tid & 15)];
        rel_sh[tid] = adj_rel[e * 16 + (tid & 15)];
    }
    {
        int r = tid >> 3;
        int c = (tid & 7) * 8;
        float part = 0.f;
        if (r < NR) {
            const float4* rp = (const float4*)(rel_emb + r * 64 + c);
            float4 aa = rp[0], bb = rp[1];
            part = aa.x * user_sh[c + 0] + aa.y * user_sh[c + 1]
                 + aa.z * user_sh[c + 2] + aa.w * user_sh[c + 3]
                 + bb.x * user_sh[c + 4] + bb.y * user_sh[c + 5]
                 + bb.z * user_sh[c + 6] + bb.w * user_sh[c + 7];
        }
        part += __shfl_down_sync(FULL, part, 4);
        part += __shfl_down_sync(FULL, part, 2);
        part += __shfl_down_sync(FULL, part, 1);
        if ((tid & 7) == 0 && r < NR) urel_sh[r] = part;
    }
    __syncthreads();

    // ---- Phase C: fused softmax + float4 aggregation, per-warp independent ----
    {
        const int hlf16 = lane & 16;           // 0 | 16: which half / row
        const int k15   = lane & 15;           // neighbor idx (softmax) / chunk idx
        const int myrow = 2 * w + (lane >> 4);
        const float4* entf4 = (const float4*)ent_emb;

        // softmax over 16 neighbors, width-16 butterflies
        float s = urel_sh[rel_sh[(myrow << 4) + k15]];
        float mx = s;
        mx = fmaxf(mx, __shfl_xor_sync(FULL, mx, 8));
        mx = fmaxf(mx, __shfl_xor_sync(FULL, mx, 4));
        mx = fmaxf(mx, __shfl_xor_sync(FULL, mx, 2));
        mx = fmaxf(mx, __shfl_xor_sync(FULL, mx, 1));
        float ev = __expf(s - mx);
        float sm = ev;
        sm += __shfl_xor_sync(FULL, sm, 8);
        sm += __shfl_xor_sync(FULL, sm, 4);
        sm += __shfl_xor_sync(FULL, sm, 2);
        sm += __shfl_xor_sync(FULL, sm, 1);
        float p = __fdividef(ev, sm);

        // aggregation: lane accumulates its float4 chunk of its row
        const int* nb = &nbr_sh[myrow << 4];
        float4 acc = make_float4(0.f, 0.f, 0.f, 0.f);
        #pragma unroll
        for (int k = 0; k < 16; k++) {
            float pk = __shfl_sync(FULL, p, hlf16 + k);
            float4 e = entf4[(nb[k] << 4) + k15];
            acc.x = fmaf(pk, e.x, acc.x);
            acc.y = fmaf(pk, e.y, acc.y);
            acc.z = fmaf(pk, e.z, acc.z);
            acc.w = fmaf(pk, e.w, acc.w);
        }
        float4 sv = entf4[(nbr_sh[256 + myrow] << 4) + k15];
        ((float4*)x_sh[myrow])[k15] =
            make_float4(sv.x + acc.x, sv.y + acc.y, sv.z + acc.z, sv.w + acc.w);

        if (w == 0) {
            // hop-0 (row 16): both halves duplicate, store once
            float s2 = urel_sh[rel_sh[256 + k15]];
            float mx2 = s2;
            mx2 = fmaxf(mx2, __shfl_xor_sync(FULL, mx2, 8));
            mx2 = fmaxf(mx2, __shfl_xor_sync(FULL, mx2, 4));
            mx2 = fmaxf(mx2, __shfl_xor_sync(FULL, mx2, 2));
            mx2 = fmaxf(mx2, __shfl_xor_sync(FULL, mx2, 1));
            float ev2 = __expf(s2 - mx2);
            float sm2 = ev2;
            sm2 += __shfl_xor_sync(FULL, sm2, 8);
            sm2 += __shfl_xor_sync(FULL, sm2, 4);
            sm2 += __shfl_xor_sync(FULL, sm2, 2);
            sm2 += __shfl_xor_sync(FULL, sm2, 1);
            float p2 = __fdividef(ev2, sm2);
            if (lane < 16) attn16_sh[lane] = p2;

            float4 acc2 = make_float4(0.f, 0.f, 0.f, 0.f);
            #pragma unroll
            for (int k = 0; k < 16; k++) {
                float pk = __shfl_sync(FULL, p2, hlf16 + k);
                float4 e = entf4[(nbr_sh[256 + k] << 4) + k15];
                acc2.x = fmaf(pk, e.x, acc2.x);
                acc2.y = fmaf(pk, e.y, acc2.y);
                acc2.z = fmaf(pk, e.z, acc2.z);
                acc2.w = fmaf(pk, e.w, acc2.w);
            }
            float4 sv2 = entf4[(vidx << 4) + k15];
            if (lane < 16)
                ((float4*)x_sh[16])[k15] = make_float4(
                    sv2.x + acc2.x, sv2.y + acc2.y, sv2.z + acc2.z, sv2.w + acc2.w);
        }
    }
    __syncthreads();

    // ---- W half-column -> 32 registers ----
    float Wreg[32];
    #pragma unroll
    for (int d = 0; d < 32; d++) Wreg[d] = Wg[(half * 32 + d) * 64 + col];

    // ---- Matvec: pair p handles rows 8p..8p+7 (+row 16 for pair 0) ----
    {
        float acc[9];
        #pragma unroll
        for (int r = 0; r < 9; r++) acc[r] = 0.f;
        const int rbase = pair << 3;
        #pragma unroll
        for (int q = 0; q < 8; q++) {
            float w0 = Wreg[4*q+0], w1 = Wreg[4*q+1];
            float w2 = Wreg[4*q+2], w3 = Wreg[4*q+3];
            #pragma unroll
            for (int r = 0; r < 8; r++) {
                float4 v = *(const float4*)&x_sh[rbase + r][half * 32 + 4*q];
                acc[r] = fmaf(v.x, w0, acc[r]);
                acc[r] = fmaf(v.y, w1, acc[r]);
                acc[r] = fmaf(v.z, w2, acc[r]);
                acc[r] = fmaf(v.w, w3, acc[r]);
            }
            if (pair == 0) {
                float4 v = *(const float4*)&x_sh[16][half * 32 + 4*q];
                acc[8] = fmaf(v.x, w0, acc[8]);
                acc[8] = fmaf(v.y, w1, acc[8]);
                acc[8] = fmaf(v.z, w2, acc[8]);
                acc[8] = fmaf(v.w, w3, acc[8]);
            }
        }
        if (half == 1) {
            #pragma unroll
            for (int r = 0; r < 8; r++) part_sh[rbase + r][col] = acc[r];
            if (pair == 0) part_sh[16][col] = acc[8];
        }
        __syncthreads();
        if (half == 0) {
            #pragma unroll
            for (int r = 0; r < 8; r++)
                h1_sh[(rbase + r) * 64 + col] =
                    sigmoidf_(acc[r] + part_sh[rbase + r][col] + breg);
            if (pair == 0)
                h0_sh[col] = sigmoidf_(acc[8] + part_sh[16][col] + breg);
        }
    }
    __syncthreads();

    // ---- Phase D: iter-1 (threads 0..127 only) ----
    if (tid < 128) {
        if (tid < 64) {
            float a0 = 0.f, a1 = 0.f, a2 = 0.f, a3 = 0.f;
            #pragma unroll
            for (int k = 0; k < 16; k += 4) {
                a0 = fmaf(attn16_sh[k + 0], h1_sh[(k + 0) * 64 + col], a0);
                a1 = fmaf(attn16_sh[k + 1], h1_sh[(k + 1) * 64 + col], a1);
                a2 = fmaf(attn16_sh[k + 2], h1_sh[(k + 2) * 64 + col], a2);
                a3 = fmaf(attn16_sh[k + 3], h1_sh[(k + 3) * 64 + col], a3);
            }
            x2_sh[col] = h0_sh[col] + ((a0 + a1) + (a2 + a3));
        }
        asm volatile("bar.sync 1, 128;" ::: "memory");

        // pair matvec on x2: half h covers d in [32h, 32h+32)
        float y0 = 0.f, y1 = 0.f, y2a = 0.f, y3 = 0.f;
        {
            const float4* xv = (const float4*)&x2_sh[half * 32];
            #pragma unroll
            for (int q = 0; q < 8; q += 4) {
                float4 v0 = xv[q + 0], v1 = xv[q + 1], v2 = xv[q + 2], v3 = xv[q + 3];
                y0 = fmaf(v0.x, Wreg[4*q+0],  y0); y0 = fmaf(v0.y, Wreg[4*q+1],  y0);
                y0 = fmaf(v0.z, Wreg[4*q+2],  y0); y0 = fmaf(v0.w, Wreg[4*q+3],  y0);
                y1 = fmaf(v1.x, Wreg[4*q+4],  y1); y1 = fmaf(v1.y, Wreg[4*q+5],  y1);
                y1 = fmaf(v1.z, Wreg[4*q+6],  y1); y1 = fmaf(v1.w, Wreg[4*q+7],  y1);
                y2a = fmaf(v2.x, Wreg[4*q+8],  y2a); y2a = fmaf(v2.y, Wreg[4*q+9],  y2a);
                y2a = fmaf(v2.z, Wreg[4*q+10], y2a); y2a = fmaf(v2.w, Wreg[4*q+11], y2a);
                y3 = fmaf(v3.x, Wreg[4*q+12], y3); y3 = fmaf(v3.y, Wreg[4*q+13], y3);
                y3 = fmaf(v3.z, Wreg[4*q+14], y3); y3 = fmaf(v3.w, Wreg[4*q+15], y3);
            }
        }
        float yp = (y0 + y1) + (y2a + y3);
        if (half == 1) part_sh[0][col] = yp;
        asm volatile("bar.sync 1, 128;" ::: "memory");

        if (tid < 64) {
            float item = tanhf(yp + part_sh[0][col] + breg);
            float t = user_sh[col] * item;
            t += __shfl_xor_sync(FULL, t, 16);
            t += __shfl_xor_sync(FULL, t, 8);
            t += __shfl_xor_sync(FULL, t, 4);
            t += __shfl_xor_sync(FULL, t, 2);
            t += __shfl_xor_sync(FULL, t, 1);
            if (lane == 0) red_sh[w] = t;
            asm volatile("bar.sync 2, 64;" ::: "memory");
            if (tid == 0)
                out[b] = sigmoidf_(red_sh[0] + red_sh[1]);
        }
    }
}

extern "C" void kernel_launch(void* const* d_in, const int* in_sizes, int n_in,
                              void* d_out, int out_size) {
    const int*   U       = (const int*)d_in[0];
    const int*   V       = (const int*)d_in[1];
    const int*   adj_ent = (const int*)d_in[2];
    const int*   adj_rel = (const int*)d_in[3];
    const float* usr_emb = (const float*)d_in[4];
    const float* rel_emb = (const float*)d_in[5];
    const float* ent_emb = (const float*)d_in[6];
    const float* W       = (const float*)d_in[7];
    const float* bvec    = (const float*)d_in[8];
    float* out = (float*)d_out;

    const int B  = in_sizes[0];
    const int NR = in_sizes[5] / 64;

    kgcn_kernel<<<B, 256>>>(U, V, adj_ent, adj_rel, usr_emb, rel_emb,
                            ent_emb, W, bvec, out, NR);
}

// round 5
// speedup vs baseline: 1.8337x; 1.1769x over previous
#include <cuda_runtime.h>

#define FULL 0xffffffffu

__device__ __forceinline__ float sigmoidf_(float y) {
    return __fdividef(1.f, 1.f + __expf(-y));
}

// KGCN fused: one CTA per TWO batch elements, 256 threads = 4 groups of 64.
// Doubles independent work per warp (34 gathers in flight), halves per-CTA
// fixed costs and wave count. W half-column in 32 regs (pair split).
__global__ void __launch_bounds__(256, 3) kgcn_kernel(
    const int* __restrict__ U, const int* __restrict__ V,
    const int* __restrict__ adj_ent, const int* __restrict__ adj_rel,
    const float* __restrict__ usr_emb, const float* __restrict__ rel_emb,
    const float* __restrict__ ent_emb, const float* __restrict__ Wg,
    const float* __restrict__ bg, float* __restrict__ out, int NR)
{
    __shared__ float user_sh[2][64];
    __shared__ float urel_sh[2][32];
    __shared__ int   nbr_sh[2][272];   // [0..255] hop2 ents, [256..271] hop1 ents
    __shared__ int   rel_sh[2][272];
    __shared__ float attn16_sh[2][16];
    __shared__ float b_sh[64];
    __shared__ __align__(16) float x_sh[2][17][64];      // pre-matvec activations
    __shared__ __align__(16) float part_sh[2][2][17][64];// [half][elem] partial dots
    __shared__ __align__(16) float h1_sh[2][16][64];
    __shared__ float h0_sh[2][64];
    __shared__ __align__(16) float x2_sh[2][64];
    __shared__ float fin_sh[2][64];
    __shared__ float red_sh[2][2];

    const int tid  = threadIdx.x;
    const int g    = tid >> 6;
    const int col  = tid & 63;
    const int lane = tid & 31;
    const int w    = tid >> 5;
    const int pair = g >> 1;
    const int half = g & 1;

    const int b0 = 2 * blockIdx.x;
    const int v0 = V[b0], v1 = V[b0 + 1];
    const int u0 = U[b0], u1 = U[b0 + 1];

    // ---- Phase A: stage users, hop-1 adjacency, bias; W -> regs (overlap) ----
    if (tid < 64)                 user_sh[0][tid]      = usr_emb[u0 * 64 + tid];
    else if (tid < 128)           user_sh[1][tid - 64] = usr_emb[u1 * 64 + (tid - 64)];
    else if (tid < 160) {
        int e = (tid - 128) >> 4, j = tid & 15;
        int vv = e ? v1 : v0;
        nbr_sh[e][256 + j] = adj_ent[vv * 16 + j];
        rel_sh[e][256 + j] = adj_rel[vv * 16 + j];
    }
    else if (tid < 224)           b_sh[tid - 160] = bg[tid - 160];
    float Wreg[32];
    #pragma unroll
    for (int d = 0; d < 32; d++) Wreg[d] = Wg[(half * 32 + d) * 64 + col];
    __syncthreads();

    // ---- Phase B: hop-2 adjacency (both elems) + urel tables ----
    {
        int p0 = nbr_sh[0][256 + (tid >> 4)];
        int p1 = nbr_sh[1][256 + (tid >> 4)];
        int j = tid & 15;
        nbr_sh[0][tid] = adj_ent[p0 * 16 + j];
        rel_sh[0][tid] = adj_rel[p0 * 16 + j];
        nbr_sh[1][tid] = adj_ent[p1 * 16 + j];
        rel_sh[1][tid] = adj_rel[p1 * 16 + j];
    }
    {
        int r = tid >> 3;
        int c = (tid & 7) * 8;
        float pa = 0.f, pb = 0.f;
        if (r < NR) {
            const float4* rp = (const float4*)(rel_emb + r * 64 + c);
            float4 aa = rp[0], bb = rp[1];
            pa = aa.x * user_sh[0][c+0] + aa.y * user_sh[0][c+1]
               + aa.z * user_sh[0][c+2] + aa.w * user_sh[0][c+3]
               + bb.x * user_sh[0][c+4] + bb.y * user_sh[0][c+5]
               + bb.z * user_sh[0][c+6] + bb.w * user_sh[0][c+7];
            pb = aa.x * user_sh[1][c+0] + aa.y * user_sh[1][c+1]
               + aa.z * user_sh[1][c+2] + aa.w * user_sh[1][c+3]
               + bb.x * user_sh[1][c+4] + bb.y * user_sh[1][c+5]
               + bb.z * user_sh[1][c+6] + bb.w * user_sh[1][c+7];
        }
        pa += __shfl_down_sync(FULL, pa, 4);
        pb += __shfl_down_sync(FULL, pb, 4);
        pa += __shfl_down_sync(FULL, pa, 2);
        pb += __shfl_down_sync(FULL, pb, 2);
        pa += __shfl_down_sync(FULL, pa, 1);
        pb += __shfl_down_sync(FULL, pb, 1);
        if ((tid & 7) == 0 && r < NR) { urel_sh[0][r] = pa; urel_sh[1][r] = pb; }
    }
    __syncthreads();

    // ---- Phase C: fused softmax + float4 aggregation, both elems per warp ----
    {
        const int hlf16 = lane & 16;
        const int k15   = lane & 15;
        const int myrow = 2 * w + (lane >> 4);
        const float4* entf4 = (const float4*)ent_emb;

        // softmax for both elements (independent chains interleave)
        float s0 = urel_sh[0][rel_sh[0][(myrow << 4) + k15]];
        float s1 = urel_sh[1][rel_sh[1][(myrow << 4) + k15]];
        float m0 = s0, m1 = s1;
        m0 = fmaxf(m0, __shfl_xor_sync(FULL, m0, 8));
        m1 = fmaxf(m1, __shfl_xor_sync(FULL, m1, 8));
        m0 = fmaxf(m0, __shfl_xor_sync(FULL, m0, 4));
        m1 = fmaxf(m1, __shfl_xor_sync(FULL, m1, 4));
        m0 = fmaxf(m0, __shfl_xor_sync(FULL, m0, 2));
        m1 = fmaxf(m1, __shfl_xor_sync(FULL, m1, 2));
        m0 = fmaxf(m0, __shfl_xor_sync(FULL, m0, 1));
        m1 = fmaxf(m1, __shfl_xor_sync(FULL, m1, 1));
        float e0v = __expf(s0 - m0), e1v = __expf(s1 - m1);
        float q0 = e0v, q1 = e1v;
        q0 += __shfl_xor_sync(FULL, q0, 8);
        q1 += __shfl_xor_sync(FULL, q1, 8);
        q0 += __shfl_xor_sync(FULL, q0, 4);
        q1 += __shfl_xor_sync(FULL, q1, 4);
        q0 += __shfl_xor_sync(FULL, q0, 2);
        q1 += __shfl_xor_sync(FULL, q1, 2);
        q0 += __shfl_xor_sync(FULL, q0, 1);
        q1 += __shfl_xor_sync(FULL, q1, 1);
        float p0 = __fdividef(e0v, q0);
        float p1 = __fdividef(e1v, q1);

        const int* nbA = &nbr_sh[0][myrow << 4];
        const int* nbB = &nbr_sh[1][myrow << 4];
        float4 a0 = make_float4(0.f,0.f,0.f,0.f);
        float4 a1 = make_float4(0.f,0.f,0.f,0.f);
        #pragma unroll
        for (int k = 0; k < 16; k++) {
            float pk0 = __shfl_sync(FULL, p0, hlf16 + k);
            float pk1 = __shfl_sync(FULL, p1, hlf16 + k);
            float4 eA = entf4[(nbA[k] << 4) + k15];
            float4 eB = entf4[(nbB[k] << 4) + k15];
            a0.x = fmaf(pk0, eA.x, a0.x); a0.y = fmaf(pk0, eA.y, a0.y);
            a0.z = fmaf(pk0, eA.z, a0.z); a0.w = fmaf(pk0, eA.w, a0.w);
            a1.x = fmaf(pk1, eB.x, a1.x); a1.y = fmaf(pk1, eB.y, a1.y);
            a1.z = fmaf(pk1, eB.z, a1.z); a1.w = fmaf(pk1, eB.w, a1.w);
        }
        float4 svA = entf4[(nbr_sh[0][256 + myrow] << 4) + k15];
        float4 svB = entf4[(nbr_sh[1][256 + myrow] << 4) + k15];
        ((float4*)x_sh[0][myrow])[k15] =
            make_float4(svA.x + a0.x, svA.y + a0.y, svA.z + a0.z, svA.w + a0.w);
        ((float4*)x_sh[1][myrow])[k15] =
            make_float4(svB.x + a1.x, svB.y + a1.y, svB.z + a1.z, svB.w + a1.w);

        // hop-0 rows: warp 0 -> elem 0, warp 1 -> elem 1
        if (w < 2) {
            const int e = w;
            const int vv = e ? v1 : v0;
            float s2 = urel_sh[e][rel_sh[e][256 + k15]];
            float mx2 = s2;
            mx2 = fmaxf(mx2, __shfl_xor_sync(FULL, mx2, 8));
            mx2 = fmaxf(mx2, __shfl_xor_sync(FULL, mx2, 4));
            mx2 = fmaxf(mx2, __shfl_xor_sync(FULL, mx2, 2));
            mx2 = fmaxf(mx2, __shfl_xor_sync(FULL, mx2, 1));
            float ev2 = __expf(s2 - mx2);
            float sm2 = ev2;
            sm2 += __shfl_xor_sync(FULL, sm2, 8);
            sm2 += __shfl_xor_sync(FULL, sm2, 4);
            sm2 += __shfl_xor_sync(FULL, sm2, 2);
            sm2 += __shfl_xor_sync(FULL, sm2, 1);
            float p2 = __fdividef(ev2, sm2);
            if (lane < 16) attn16_sh[e][lane] = p2;

            float4 acc2 = make_float4(0.f,0.f,0.f,0.f);
            #pragma unroll
            for (int k = 0; k < 16; k++) {
                float pk = __shfl_sync(FULL, p2, hlf16 + k);
                float4 ee = entf4[(nbr_sh[e][256 + k] << 4) + k15];
                acc2.x = fmaf(pk, ee.x, acc2.x);
                acc2.y = fmaf(pk, ee.y, acc2.y);
                acc2.z = fmaf(pk, ee.z, acc2.z);
                acc2.w = fmaf(pk, ee.w, acc2.w);
            }
            float4 sv2 = entf4[(vv << 4) + k15];
            if (lane < 16)
                ((float4*)x_sh[e][16])[k15] = make_float4(
                    sv2.x + acc2.x, sv2.y + acc2.y, sv2.z + acc2.z, sv2.w + acc2.w);
        }
    }
    __syncthreads();

    // ---- Matvec: pair p -> rows 8p..8p+7 (+16 for pair0), both elems ----
    {
        const int rbase = pair << 3;
        #pragma unroll
        for (int e = 0; e < 2; e++) {
            float acc[9];
            #pragma unroll
            for (int r = 0; r < 9; r++) acc[r] = 0.f;
            #pragma unroll
            for (int q = 0; q < 8; q++) {
                float w0 = Wreg[4*q+0], w1 = Wreg[4*q+1];
                float w2 = Wreg[4*q+2], w3 = Wreg[4*q+3];
                #pragma unroll
                for (int r = 0; r < 8; r++) {
                    float4 v = *(const float4*)&x_sh[e][rbase + r][half * 32 + 4*q];
                    acc[r] = fmaf(v.x, w0, acc[r]);
                    acc[r] = fmaf(v.y, w1, acc[r]);
                    acc[r] = fmaf(v.z, w2, acc[r]);
                    acc[r] = fmaf(v.w, w3, acc[r]);
                }
                if (pair == 0) {
                    float4 v = *(const float4*)&x_sh[e][16][half * 32 + 4*q];
                    acc[8] = fmaf(v.x, w0, acc[8]);
                    acc[8] = fmaf(v.y, w1, acc[8]);
                    acc[8] = fmaf(v.z, w2, acc[8]);
                    acc[8] = fmaf(v.w, w3, acc[8]);
                }
            }
            #pragma unroll
            for (int r = 0; r < 8; r++) part_sh[half][e][rbase + r][col] = acc[r];
            if (pair == 0) part_sh[half][e][16][col] = acc[8];
        }
    }
    __syncthreads();

    // ---- Combine: h = sigmoid(partA + partB + b), flat distribution ----
    for (int i = tid; i < 2 * 17 * 64; i += 256) {
        int e = (i >= 1088);
        int rem = i - e * 1088;
        int row = rem >> 6, c = rem & 63;
        float hv = sigmoidf_(part_sh[0][e][row][c] + part_sh[1][e][row][c] + b_sh[c]);
        if (row < 16) h1_sh[e][row][c] = hv;
        else          h0_sh[e][c] = hv;
    }
    __syncthreads();

    // ---- Phase D: pair p handles element p's iter-1 + final score ----
    {
        const int e = pair;
        const int tidp = tid - (pair << 7);       // 0..127 within pair
        const int barW = 1 + 2 * pair;            // 128-wide barrier id
        const int barN = 2 + 2 * pair;            // 64-wide barrier id

        if (tidp < 64) {
            float a0 = 0.f, a1 = 0.f, a2 = 0.f, a3 = 0.f;
            #pragma unroll
            for (int k = 0; k < 16; k += 4) {
                a0 = fmaf(attn16_sh[e][k + 0], h1_sh[e][k + 0][col], a0);
                a1 = fmaf(attn16_sh[e][k + 1], h1_sh[e][k + 1][col], a1);
                a2 = fmaf(attn16_sh[e][k + 2], h1_sh[e][k + 2][col], a2);
                a3 = fmaf(attn16_sh[e][k + 3], h1_sh[e][k + 3][col], a3);
            }
            x2_sh[e][col] = h0_sh[e][col] + ((a0 + a1) + (a2 + a3));
        }
        asm volatile("bar.sync %0, 128;" :: "r"(barW) : "memory");

        float y0 = 0.f, y1 = 0.f, y2a = 0.f, y3 = 0.f;
        {
            const float4* xv = (const float4*)&x2_sh[e][half * 32];
            #pragma unroll
            for (int q = 0; q < 8; q += 4) {
                float4 v0 = xv[q + 0], v1 = xv[q + 1], v2 = xv[q + 2], v3 = xv[q + 3];
                y0 = fmaf(v0.x, Wreg[4*q+0],  y0); y0 = fmaf(v0.y, Wreg[4*q+1],  y0);
                y0 = fmaf(v0.z, Wreg[4*q+2],  y0); y0 = fmaf(v0.w, Wreg[4*q+3],  y0);
                y1 = fmaf(v1.x, Wreg[4*q+4],  y1); y1 = fmaf(v1.y, Wreg[4*q+5],  y1);
                y1 = fmaf(v1.z, Wreg[4*q+6],  y1); y1 = fmaf(v1.w, Wreg[4*q+7],  y1);
                y2a = fmaf(v2.x, Wreg[4*q+8],  y2a); y2a = fmaf(v2.y, Wreg[4*q+9],  y2a);
                y2a = fmaf(v2.z, Wreg[4*q+10], y2a); y2a = fmaf(v2.w, Wreg[4*q+11], y2a);
                y3 = fmaf(v3.x, Wreg[4*q+12], y3); y3 = fmaf(v3.y, Wreg[4*q+13], y3);
                y3 = fmaf(v3.z, Wreg[4*q+14], y3); y3 = fmaf(v3.w, Wreg[4*q+15], y3);
            }
        }
        float yp = (y0 + y1) + (y2a + y3);
        if (half == 1) fin_sh[e][col] = yp;
        asm volatile("bar.sync %0, 128;" :: "r"(barW) : "memory");

        if (tidp < 64) {
            float item = tanhf(yp + fin_sh[e][col] + b_sh[col]);
            float t = user_sh[e][col] * item;
            t += __shfl_xor_sync(FULL, t, 16);
            t += __shfl_xor_sync(FULL, t, 8);
            t += __shfl_xor_sync(FULL, t, 4);
            t += __shfl_xor_sync(FULL, t, 2);
            t += __shfl_xor_sync(FULL, t, 1);
            if (lane == 0) red_sh[e][(tidp >> 5)] = t;
            asm volatile("bar.sync %0, 64;" :: "r"(barN) : "memory");
            if (tidp == 0)
                out[b0 + e] = sigmoidf_(red_sh[e][0] + red_sh[e][1]);
        }
    }
}

extern "C" void kernel_launch(void* const* d_in, const int* in_sizes, int n_in,
                              void* d_out, int out_size) {
    const int*   U       = (const int*)d_in[0];
    const int*   V       = (const int*)d_in[1];
    const int*   adj_ent = (const int*)d_in[2];
    const int*   adj_rel = (const int*)d_in[3];
    const float* usr_emb = (const float*)d_in[4];
    const float* rel_emb = (const float*)d_in[5];
    const float* ent_emb = (const float*)d_in[6];
    const float* W       = (const float*)d_in[7];
    const float* bvec    = (const float*)d_in[8];
    float* out = (float*)d_out;

    const int B  = in_sizes[0];
    const int NR = in_sizes[5] / 64;

    kgcn_kernel<<<B / 2, 256>>>(U, V, adj_ent, adj_rel, usr_emb, rel_emb,
                                ent_emb, W, bvec, out, NR);
}

// round 6
// speedup vs baseline: 1.8691x; 1.0193x over previous
#include <cuda_runtime.h>

#define FULL 0xffffffffu

__device__ __forceinline__ float sigmoidf_(float y) {
    return __fdividef(1.f, 1.f + __expf(-y));
}

// KGCN fused: one CTA per FOUR batch elements, 256 threads = 4 groups of 64.
// 68 independent gathers in flight per warp; W/adjacency staging amortized 4x.
// Smem recycled: h outputs overwrite x_sh, partials ping-pong in [2][17][64].
__global__ void __launch_bounds__(256, 3) kgcn_kernel(
    const int* __restrict__ U, const int* __restrict__ V,
    const int* __restrict__ adj_ent, const int* __restrict__ adj_rel,
    const float* __restrict__ usr_emb, const float* __restrict__ rel_emb,
    const float* __restrict__ ent_emb, const float* __restrict__ Wg,
    const float* __restrict__ bg, float* __restrict__ out, int NR)
{
    __shared__ float user_sh[4][64];
    __shared__ float urel_sh[4][32];
    __shared__ int   nbr_sh[4][272];   // [0..255] hop2 ents, [256..271] hop1 ents
    __shared__ int   rel_sh[4][272];
    __shared__ float attn16_sh[4][16];
    __shared__ float b_sh[64];
    __shared__ __align__(16) float x_sh[4][17][64];   // activations, then h outputs
    __shared__ __align__(16) float part_sh[2][17][64];// ping-pong half-1 partials
    __shared__ __align__(16) float x2_sh[4][64];
    __shared__ float fin_sh[4][64];
    __shared__ float red_sh[4][2];

    const int tid  = threadIdx.x;
    const int g    = tid >> 6;
    const int col  = tid & 63;
    const int lane = tid & 31;
    const int w    = tid >> 5;
    const int pair = g >> 1;
    const int half = g & 1;

    const int b0 = 4 * blockIdx.x;
    int uu[4], vv[4];
    #pragma unroll
    for (int e = 0; e < 4; e++) { uu[e] = U[b0 + e]; vv[e] = V[b0 + e]; }

    // ---- Phase A: stage users, hop-1 adjacency, bias; W -> regs ----
    user_sh[tid >> 6][col] = usr_emb[uu[tid >> 6] * 64 + col];
    if (tid < 64) {
        int e = tid >> 4, j = tid & 15;
        nbr_sh[e][256 + j] = adj_ent[vv[e] * 16 + j];
        rel_sh[e][256 + j] = adj_rel[vv[e] * 16 + j];
    } else if (tid < 128) {
        b_sh[tid - 64] = bg[tid - 64];
    }
    float Wreg[32];
    #pragma unroll
    for (int d = 0; d < 32; d++) Wreg[d] = Wg[(half * 32 + d) * 64 + col];
    __syncthreads();

    // ---- Phase B: hop-2 adjacency (4 elems) + urel tables ----
    {
        int j = tid & 15, pr = tid >> 4;
        #pragma unroll
        for (int e = 0; e < 4; e++) {
            int p = nbr_sh[e][256 + pr];
            nbr_sh[e][tid] = adj_ent[p * 16 + j];
            rel_sh[e][tid] = adj_rel[p * 16 + j];
        }
    }
    {
        int r = tid >> 3;
        int c = (tid & 7) * 8;
        float pa[4] = {0.f, 0.f, 0.f, 0.f};
        if (r < NR) {
            const float4* rp = (const float4*)(rel_emb + r * 64 + c);
            float4 aa = rp[0], bb = rp[1];
            #pragma unroll
            for (int e = 0; e < 4; e++)
                pa[e] = aa.x * user_sh[e][c+0] + aa.y * user_sh[e][c+1]
                      + aa.z * user_sh[e][c+2] + aa.w * user_sh[e][c+3]
                      + bb.x * user_sh[e][c+4] + bb.y * user_sh[e][c+5]
                      + bb.z * user_sh[e][c+6] + bb.w * user_sh[e][c+7];
        }
        #pragma unroll
        for (int o = 4; o > 0; o >>= 1) {
            #pragma unroll
            for (int e = 0; e < 4; e++)
                pa[e] += __shfl_down_sync(FULL, pa[e], o);
        }
        if ((tid & 7) == 0 && r < NR) {
            #pragma unroll
            for (int e = 0; e < 4; e++) urel_sh[e][r] = pa[e];
        }
    }
    __syncthreads();

    // ---- Phase C: fused softmax + float4 aggregation, 4 elems per warp ----
    {
        const int hlf16 = lane & 16;
        const int k15   = lane & 15;
        const int myrow = 2 * w + (lane >> 4);
        const float4* entf4 = (const float4*)ent_emb;

        float sc[4], mx[4], ev[4], sm[4], pp[4];
        #pragma unroll
        for (int e = 0; e < 4; e++)
            sc[e] = urel_sh[e][rel_sh[e][(myrow << 4) + k15]];
        #pragma unroll
        for (int e = 0; e < 4; e++) mx[e] = sc[e];
        #pragma unroll
        for (int o = 8; o > 0; o >>= 1) {
            #pragma unroll
            for (int e = 0; e < 4; e++)
                mx[e] = fmaxf(mx[e], __shfl_xor_sync(FULL, mx[e], o));
        }
        #pragma unroll
        for (int e = 0; e < 4; e++) { ev[e] = __expf(sc[e] - mx[e]); sm[e] = ev[e]; }
        #pragma unroll
        for (int o = 8; o > 0; o >>= 1) {
            #pragma unroll
            for (int e = 0; e < 4; e++)
                sm[e] += __shfl_xor_sync(FULL, sm[e], o);
        }
        #pragma unroll
        for (int e = 0; e < 4; e++) pp[e] = __fdividef(ev[e], sm[e]);

        const int* nb[4];
        #pragma unroll
        for (int e = 0; e < 4; e++) nb[e] = &nbr_sh[e][myrow << 4];
        float4 acc[4];
        #pragma unroll
        for (int e = 0; e < 4; e++) acc[e] = make_float4(0.f, 0.f, 0.f, 0.f);
        #pragma unroll
        for (int k = 0; k < 16; k++) {
            #pragma unroll
            for (int e = 0; e < 4; e++) {
                float pk = __shfl_sync(FULL, pp[e], hlf16 + k);
                float4 t = entf4[(nb[e][k] << 4) + k15];
                acc[e].x = fmaf(pk, t.x, acc[e].x);
                acc[e].y = fmaf(pk, t.y, acc[e].y);
                acc[e].z = fmaf(pk, t.z, acc[e].z);
                acc[e].w = fmaf(pk, t.w, acc[e].w);
            }
        }
        #pragma unroll
        for (int e = 0; e < 4; e++) {
            float4 sv = entf4[(nbr_sh[e][256 + myrow] << 4) + k15];
            ((float4*)x_sh[e][myrow])[k15] = make_float4(
                sv.x + acc[e].x, sv.y + acc[e].y, sv.z + acc[e].z, sv.w + acc[e].w);
        }

        // hop-0 rows: warp e handles element e (e < 4)
        if (w < 4) {
            const int e = w;
            float s2 = urel_sh[e][rel_sh[e][256 + k15]];
            float mx2 = s2;
            mx2 = fmaxf(mx2, __shfl_xor_sync(FULL, mx2, 8));
            mx2 = fmaxf(mx2, __shfl_xor_sync(FULL, mx2, 4));
            mx2 = fmaxf(mx2, __shfl_xor_sync(FULL, mx2, 2));
            mx2 = fmaxf(mx2, __shfl_xor_sync(FULL, mx2, 1));
            float ev2 = __expf(s2 - mx2);
            float sm2 = ev2;
            sm2 += __shfl_xor_sync(FULL, sm2, 8);
            sm2 += __shfl_xor_sync(FULL, sm2, 4);
            sm2 += __shfl_xor_sync(FULL, sm2, 2);
            sm2 += __shfl_xor_sync(FULL, sm2, 1);
            float p2 = __fdividef(ev2, sm2);
            if (lane < 16) attn16_sh[e][lane] = p2;

            float4 acc2 = make_float4(0.f, 0.f, 0.f, 0.f);
            #pragma unroll
            for (int k = 0; k < 16; k++) {
                float pk = __shfl_sync(FULL, p2, hlf16 + k);
                float4 t = entf4[(nbr_sh[e][256 + k] << 4) + k15];
                acc2.x = fmaf(pk, t.x, acc2.x);
                acc2.y = fmaf(pk, t.y, acc2.y);
                acc2.z = fmaf(pk, t.z, acc2.z);
                acc2.w = fmaf(pk, t.w, acc2.w);
            }
            float4 sv2 = entf4[(vv[e] << 4) + k15];
            if (lane < 16)
                ((float4*)x_sh[e][16])[k15] = make_float4(
                    sv2.x + acc2.x, sv2.y + acc2.y, sv2.z + acc2.z, sv2.w + acc2.w);
        }
    }
    __syncthreads();

    // ---- Matvec per element: half1 stores partials (ping-pong), half0
    //      combines + writes sigmoid outputs BACK INTO x_sh[e] ----
    {
        const int rbase = pair << 3;
        for (int e = 0; e < 4; e++) {
            float acc[9];
            #pragma unroll
            for (int r = 0; r < 9; r++) acc[r] = 0.f;
            #pragma unroll
            for (int q = 0; q < 8; q++) {
                float w0 = Wreg[4*q+0], w1 = Wreg[4*q+1];
                float w2 = Wreg[4*q+2], w3 = Wreg[4*q+3];
                #pragma unroll
                for (int r = 0; r < 8; r++) {
                    float4 v = *(const float4*)&x_sh[e][rbase + r][half * 32 + 4*q];
                    acc[r] = fmaf(v.x, w0, acc[r]);
                    acc[r] = fmaf(v.y, w1, acc[r]);
                    acc[r] = fmaf(v.z, w2, acc[r]);
                    acc[r] = fmaf(v.w, w3, acc[r]);
                }
                if (pair == 0) {
                    float4 v = *(const float4*)&x_sh[e][16][half * 32 + 4*q];
                    acc[8] = fmaf(v.x, w0, acc[8]);
                    acc[8] = fmaf(v.y, w1, acc[8]);
                    acc[8] = fmaf(v.z, w2, acc[8]);
                    acc[8] = fmaf(v.w, w3, acc[8]);
                }
            }
            if (half == 1) {
                #pragma unroll
                for (int r = 0; r < 8; r++) part_sh[e & 1][rbase + r][col] = acc[r];
                if (pair == 0) part_sh[e & 1][16][col] = acc[8];
            }
            __syncthreads();
            if (half == 0) {
                #pragma unroll
                for (int r = 0; r < 8; r++)
                    x_sh[e][rbase + r][col] =
                        sigmoidf_(acc[r] + part_sh[e & 1][rbase + r][col] + b_sh[col]);
                if (pair == 0)
                    x_sh[e][16][col] =
                        sigmoidf_(acc[8] + part_sh[e & 1][16][col] + b_sh[col]);
            }
        }
    }
    __syncthreads();

    // ---- Phase D: pair p handles elements 2p, 2p+1 ----
    {
        const int e0 = 2 * pair, e1 = 2 * pair + 1;
        const int tidp = tid - (pair << 7);   // 0..127 within pair
        const int barW = 1 + pair;            // 128-wide barrier ids 1,2
        const int barN = 3 + pair;            // 64-wide barrier ids 3,4

        if (tidp < 64) {
            float a0 = 0.f, a1 = 0.f, a2 = 0.f, a3 = 0.f;
            float c0 = 0.f, c1 = 0.f, c2 = 0.f, c3 = 0.f;
            #pragma unroll
            for (int k = 0; k < 16; k += 4) {
                a0 = fmaf(attn16_sh[e0][k + 0], x_sh[e0][k + 0][col], a0);
                a1 = fmaf(attn16_sh[e0][k + 1], x_sh[e0][k + 1][col], a1);
                a2 = fmaf(attn16_sh[e0][k + 2], x_sh[e0][k + 2][col], a2);
                a3 = fmaf(attn16_sh[e0][k + 3], x_sh[e0][k + 3][col], a3);
                c0 = fmaf(attn16_sh[e1][k + 0], x_sh[e1][k + 0][col], c0);
                c1 = fmaf(attn16_sh[e1][k + 1], x_sh[e1][k + 1][col], c1);
                c2 = fmaf(attn16_sh[e1][k + 2], x_sh[e1][k + 2][col], c2);
                c3 = fmaf(attn16_sh[e1][k + 3], x_sh[e1][k + 3][col], c3);
            }
            x2_sh[e0][col] = x_sh[e0][16][col] + ((a0 + a1) + (a2 + a3));
            x2_sh[e1][col] = x_sh[e1][16][col] + ((c0 + c1) + (c2 + c3));
        }
        asm volatile("bar.sync %0, 128;" :: "r"(barW) : "memory");

        float ya = 0.f, yb = 0.f, yc = 0.f, yd = 0.f;
        {
            const float4* xv0 = (const float4*)&x2_sh[e0][half * 32];
            const float4* xv1 = (const float4*)&x2_sh[e1][half * 32];
            #pragma unroll
            for (int q = 0; q < 8; q += 2) {
                float4 v0 = xv0[q], v0b = xv0[q + 1];
                float4 v1 = xv1[q], v1b = xv1[q + 1];
                ya = fmaf(v0.x,  Wreg[4*q+0], ya); ya = fmaf(v0.y,  Wreg[4*q+1], ya);
                ya = fmaf(v0.z,  Wreg[4*q+2], ya); ya = fmaf(v0.w,  Wreg[4*q+3], ya);
                yb = fmaf(v0b.x, Wreg[4*q+4], yb); yb = fmaf(v0b.y, Wreg[4*q+5], yb);
                yb = fmaf(v0b.z, Wreg[4*q+6], yb); yb = fmaf(v0b.w, Wreg[4*q+7], yb);
                yc = fmaf(v1.x,  Wreg[4*q+0], yc); yc = fmaf(v1.y,  Wreg[4*q+1], yc);
                yc = fmaf(v1.z,  Wreg[4*q+2], yc); yc = fmaf(v1.w,  Wreg[4*q+3], yc);
                yd = fmaf(v1b.x, Wreg[4*q+4], yd); yd = fmaf(v1b.y, Wreg[4*q+5], yd);
                yd = fmaf(v1b.z, Wreg[4*q+6], yd); yd = fmaf(v1b.w, Wreg[4*q+7], yd);
            }
        }
        float yp0 = ya + yb, yp1 = yc + yd;
        if (half == 1) { fin_sh[e0][col] = yp0; fin_sh[e1][col] = yp1; }
        asm volatile("bar.sync %0, 128;" :: "r"(barW) : "memory");

        if (tidp < 64) {
            float it0 = tanhf(yp0 + fin_sh[e0][col] + b_sh[col]);
            float it1 = tanhf(yp1 + fin_sh[e1][col] + b_sh[col]);
            float t0 = user_sh[e0][col] * it0;
            float t1 = user_sh[e1][col] * it1;
            #pragma unroll
            for (int o = 16; o > 0; o >>= 1) {
                t0 += __shfl_xor_sync(FULL, t0, o);
                t1 += __shfl_xor_sync(FULL, t1, o);
            }
            if (lane == 0) { red_sh[e0][tidp >> 5] = t0; red_sh[e1][tidp >> 5] = t1; }
            asm volatile("bar.sync %0, 64;" :: "r"(barN) : "memory");
            if (tidp == 0) {
                out[b0 + e0] = sigmoidf_(red_sh[e0][0] + red_sh[e0][1]);
                out[b0 + e1] = sigmoidf_(red_sh[e1][0] + red_sh[e1][1]);
            }
        }
    }
}

extern "C" void kernel_launch(void* const* d_in, const int* in_sizes, int n_in,
                              void* d_out, int out_size) {
    const int*   U       = (const int*)d_in[0];
    const int*   V       = (const int*)d_in[1];
    const int*   adj_ent = (const int*)d_in[2];
    const int*   adj_rel = (const int*)d_in[3];
    const float* usr_emb = (const float*)d_in[4];
    const float* rel_emb = (const float*)d_in[5];
    const float* ent_emb = (const float*)d_in[6];
    const float* W       = (const float*)d_in[7];
    const float* bvec    = (const float*)d_in[8];
    float* out = (float*)d_out;

    const int B  = in_sizes[0];
    const int NR = in_sizes[5] / 64;

    kgcn_kernel<<<B / 4, 256>>>(U, V, adj_ent, adj_rel, usr_emb, rel_emb,
                                ent_emb, W, bvec, out, NR);
}